// round 8
// baseline (speedup 1.0000x reference)
#include <cuda_runtime.h>
#include <math.h>

#define HID   1024
#define BSZ   16
#define NOPT  4
#define ROWS  (BSZ*NOPT)    // 64
#define TRUN  2
#define SEQ   1536
#define PLEN  512
#define QLEN  128

#define KCHUNK 64
#define KSPLIT (HID/KCHUNK)   // 16
#define NTILE  64
#define NB     (16*KSPLIT)    // 256 CTAs; 2/SM max -> all co-resident wave 1

// Scratch (device globals — no allocation allowed)
__device__ float g_feats[ROWS*HID];
__device__ float g_h1[ROWS*HID];
__device__ float g_h2[ROWS*HID];
__device__ float g_logits[ROWS];

// Epoch barrier state. count self-resets; sense is a monotonic epoch ->
// graph-replay safe, no per-call host reset needed.
__device__ unsigned g_bar_count = 0;
__device__ unsigned g_bar_sense = 0;

// ---------------------------------------------------------------------------
// f32x2 helpers (Blackwell packed fp32 pipe; PTX-only)
// ---------------------------------------------------------------------------
__device__ __forceinline__ unsigned long long bcast_f32x2(float v) {
    unsigned long long r;
    asm("mov.b64 %0, {%1, %1};" : "=l"(r) : "r"(__float_as_uint(v)));
    return r;
}
__device__ __forceinline__ void fma_f32x2(unsigned long long& acc,
                                          unsigned long long a,
                                          unsigned long long b) {
    asm("fma.rn.f32x2 %0, %1, %2, %0;" : "+l"(acc) : "l"(a), "l"(b));
}
__device__ __forceinline__ float lo_f(unsigned long long v) {
    return __uint_as_float((unsigned)(v & 0xFFFFFFFFull));
}
__device__ __forceinline__ float hi_f(unsigned long long v) {
    return __uint_as_float((unsigned)(v >> 32));
}

__device__ __forceinline__ long long opt_at(const void* p, bool is64, int i) {
    if (is64) return ((const long long*)p)[i];
    return (long long)((const int*)p)[i];
}

__device__ __forceinline__ unsigned atomic_read(unsigned* p) {
    unsigned v;
    asm volatile("atom.global.add.u32 %0, [%1], 0;" : "=r"(v) : "l"(p) : "memory");
    return v;
}

// Epoch grid barrier. epoch0 = sense snapshot taken BEFORE the first barrier;
// barrier i waits for sense to reach epoch0 + i + 1. All NB CTAs co-resident.
__device__ __forceinline__ void grid_bar(unsigned epoch0, unsigned i) {
    __syncthreads();
    if (threadIdx.x == 0) {
        __threadfence();   // release all prior stores/reductions
        unsigned arrived = atomicAdd(&g_bar_count, 1u);
        unsigned target = epoch0 + i + 1u;
        if (arrived == NB - 1u) {
            atomicExch(&g_bar_count, 0u);   // reset before release
            __threadfence();
            atomicAdd(&g_bar_sense, 1u);
        } else {
            while ((int)(atomic_read(&g_bar_sense) - target) < 0)
                __nanosleep(32);
        }
        __threadfence();   // acquire
    }
    __syncthreads();
}

// ---------------------------------------------------------------------------
// GEMM phase: out += A(64x1024) @ W(1024x1024) chunk. 64x64 tile, k-chunk 64.
// cta -> n0=(cta&15)*64, k0=(cta>>4)*64. 4x4 micro via FFMA2, REDG epilogue.
// ---------------------------------------------------------------------------
template <int LAYER>
__device__ __forceinline__ void gemm_phase(const float* __restrict__ W,
                                           const float* __restrict__ A,
                                           float* __restrict__ out,
                                           float (*As)[68], float (*Ws)[64],
                                           int cta, int tid) {
    const int n0 = (cta & 15) * NTILE;
    const int k0 = (cta >> 4) * KCHUNK;

    // Load A tile 64 rows x 64 k, float4 over k, store transposed [k][row].
    {
        int k4 = (tid & 15) * 4;          // 0..60
        int r  = tid >> 4;                // 0..15
        #pragma unroll
        for (int rr = 0; rr < 4; rr++) {
            int row = r + rr * 16;
            float4 v;
            if (LAYER == 1) {
                v = __ldcg((const float4*)(A + (size_t)row * HID + k0 + k4));
                v.x = fmaxf(v.x, 0.f); v.y = fmaxf(v.y, 0.f);
                v.z = fmaxf(v.z, 0.f); v.w = fmaxf(v.w, 0.f);
            } else {
                v = *(const float4*)(A + (size_t)row * HID + k0 + k4);
            }
            As[k4 + 0][row] = v.x;
            As[k4 + 1][row] = v.y;
            As[k4 + 2][row] = v.z;
            As[k4 + 3][row] = v.w;
        }
    }
    // Load W tile 64 k x 64 n, float4 over n.
    {
        int c4 = (tid & 15) * 4;
        int kk = tid >> 4;
        #pragma unroll
        for (int i = 0; i < 4; i++) {
            int k = kk + i * 16;
            *(float4*)&Ws[k][c4] =
                *(const float4*)(W + (size_t)(k0 + k) * HID + n0 + c4);
        }
    }
    __syncthreads();

    const int c0 = (tid & 15) * 4;
    const int r0 = (tid >> 4) * 4;

    unsigned long long accP[4][2] = {};
    #pragma unroll 16
    for (int kk = 0; kk < KCHUNK; kk++) {
        ulonglong2 ap = *(const ulonglong2*)&As[kk][r0];   // packed row pairs
        float4 w = *(const float4*)&Ws[kk][c0];
        unsigned long long w0 = bcast_f32x2(w.x);
        unsigned long long w1 = bcast_f32x2(w.y);
        unsigned long long w2 = bcast_f32x2(w.z);
        unsigned long long w3 = bcast_f32x2(w.w);
        fma_f32x2(accP[0][0], ap.x, w0); fma_f32x2(accP[0][1], ap.y, w0);
        fma_f32x2(accP[1][0], ap.x, w1); fma_f32x2(accP[1][1], ap.y, w1);
        fma_f32x2(accP[2][0], ap.x, w2); fma_f32x2(accP[2][1], ap.y, w2);
        fma_f32x2(accP[3][0], ap.x, w3); fma_f32x2(accP[3][1], ap.y, w3);
    }

    #pragma unroll
    for (int i = 0; i < 4; i++) {
        int h = i >> 1;
        float v0 = (i & 1) ? hi_f(accP[0][h]) : lo_f(accP[0][h]);
        float v1 = (i & 1) ? hi_f(accP[1][h]) : lo_f(accP[1][h]);
        float v2 = (i & 1) ? hi_f(accP[2][h]) : lo_f(accP[2][h]);
        float v3 = (i & 1) ? hi_f(accP[3][h]) : lo_f(accP[3][h]);
        float* p = out + (size_t)(r0 + i) * HID + n0 + c0;
        asm volatile("red.global.add.v4.f32 [%0], {%1, %2, %3, %4};"
                     :: "l"(p), "f"(v0), "f"(v1), "f"(v2), "f"(v3) : "memory");
    }
    __syncthreads();   // protect smem reuse by the next phase
}

// ---------------------------------------------------------------------------
// Single persistent kernel: prep | GEMM0 | GEMM1 | gemv | loss
// 256 CTAs x 256 threads, <=2 CTAs/SM -> all co-resident (barrier-safe).
// ---------------------------------------------------------------------------
__global__ void __launch_bounds__(256)
fused_kernel(const float* __restrict__ emb, const void* __restrict__ opt_length,
             const float* __restrict__ b1, const float* __restrict__ b2,
             const float* __restrict__ W1, const float* __restrict__ W2,
             const float* __restrict__ W3, const int* __restrict__ y,
             float* __restrict__ out, int out_size) {
    __shared__ float As[KCHUNK][68];
    __shared__ float Ws[KCHUNK][64];
    __shared__ float red[8];
    __shared__ unsigned s_epoch;

    const int cta = blockIdx.x;
    const int tid = threadIdx.x;

    if (tid == 0) s_epoch = atomic_read(&g_bar_sense);   // pre-release snapshot
    __syncthreads();
    const unsigned epoch0 = s_epoch;

    // ---- phase 0: feats (CTAs 0..63), bias-init (CTAs 64..191) ----
    if (cta < ROWS) {
        int row = cta;
        int b = row >> 2, o = row & 3;
        bool is64 = (((const int*)opt_length)[1] == 0);
        long long cs = 0;
        for (int i = 0; i <= o; i++) cs += opt_at(opt_length, is64, i);
        int ohead = PLEN + QLEN + (int)cs;
        int otail = ohead + (int)opt_at(opt_length, is64, o + 1) - 1;
        int pos[6] = {0, PLEN - 1, PLEN, PLEN + QLEN - 1, ohead, otail};

        int h4 = tid * 4;
        float4 acc = make_float4(0.f, 0.f, 0.f, 0.f);
        #pragma unroll
        for (int t = 0; t < TRUN; t++) {
            const float* base = emb + (size_t)(t * BSZ + b) * SEQ * HID;
            #pragma unroll
            for (int p = 0; p < 6; p++) {
                float4 v = *(const float4*)(base + (size_t)pos[p] * HID + h4);
                acc.x += v.x; acc.y += v.y; acc.z += v.z; acc.w += v.w;
            }
        }
        const float s = 0.25f;
        *(float4*)(g_feats + (size_t)row * HID + h4) =
            make_float4(acc.x * s, acc.y * s, acc.z * s, acc.w * s);
    } else if (cta < 2 * ROWS) {
        int row = cta - ROWS;
        int h4 = tid * 4;
        *(float4*)(g_h1 + (size_t)row * HID + h4) = *(const float4*)(b1 + h4);
    } else if (cta < 3 * ROWS) {
        int row = cta - 2 * ROWS;
        int h4 = tid * 4;
        *(float4*)(g_h2 + (size_t)row * HID + h4) = *(const float4*)(b2 + h4);
    }

    grid_bar(epoch0, 0);

    // ---- phase 1: h1 += feats @ W1 ----
    gemm_phase<0>(W1, g_feats, g_h1, As, Ws, cta, tid);

    grid_bar(epoch0, 1);

    // ---- phase 2: h2 += relu(h1) @ W2 ----
    gemm_phase<1>(W2, g_h1, g_h2, As, Ws, cta, tid);

    grid_bar(epoch0, 2);

    // ---- phase 3: gemv, CTAs 0..63, one row each ----
    if (cta < ROWS) {
        const float* h = g_h2 + (size_t)cta * HID;
        float4 hv = __ldcg((const float4*)(h + tid * 4));   // L1-bypass
        float4 wv = *(const float4*)(W3 + tid * 4);
        float s = fmaxf(hv.x, 0.f) * wv.x + fmaxf(hv.y, 0.f) * wv.y
                + fmaxf(hv.z, 0.f) * wv.z + fmaxf(hv.w, 0.f) * wv.w;
        #pragma unroll
        for (int off = 16; off; off >>= 1)
            s += __shfl_down_sync(0xFFFFFFFFu, s, off);
        if ((tid & 31) == 0) red[tid >> 5] = s;
        __syncthreads();
        if (tid == 0) {
            float logit = 0.f;
            #pragma unroll
            for (int i = 0; i < 8; i++) logit += red[i];
            g_logits[cta] = logit;
            if (out_size >= ROWS) out[cta] = logit;
        }
    }

    grid_bar(epoch0, 3);

    // ---- phase 4: log_softmax loss (CTA 0, one warp) ----
    if (cta == 0 && tid < 32) {
        float l[NOPT];
        float loss_part = 0.f;
        if (tid < BSZ) {
            float m = -1e30f;
            #pragma unroll
            for (int o = 0; o < NOPT; o++) {
                l[o] = __ldcg(&g_logits[tid * NOPT + o]);
                m = fmaxf(m, l[o]);
            }
            float se = 0.f;
            #pragma unroll
            for (int o = 0; o < NOPT; o++) se += expf(l[o] - m);
            float lse = m + logf(se);
            loss_part = -(l[y[tid]] - lse);
        }
        #pragma unroll
        for (int off = 16; off; off >>= 1)
            loss_part += __shfl_down_sync(0xFFFFFFFFu, loss_part, off);
        if (tid == 0) {
            float loss = loss_part / (float)BSZ;
            if (out_size == 1)             out[0] = loss;
            else if (out_size >= ROWS + 1) out[ROWS] = loss;
        }
    }
}

// ---------------------------------------------------------------------------
// Launch — ONE kernel
// inputs: 0=embeddings 1=W1 2=b1 3=W2 4=b2 5=W3 6=y 7=opt_length
// ---------------------------------------------------------------------------
extern "C" void kernel_launch(void* const* d_in, const int* in_sizes, int n_in,
                              void* d_out, int out_size) {
    const float* emb = (const float*)d_in[0];
    const float* W1  = (const float*)d_in[1];
    const float* b1  = (const float*)d_in[2];
    const float* W2  = (const float*)d_in[3];
    const float* b2  = (const float*)d_in[4];
    const float* W3  = (const float*)d_in[5];
    const int*   y   = (const int*)d_in[6];
    const void*  opt = (const void*)d_in[7];
    float* out = (float*)d_out;

    fused_kernel<<<NB, 256>>>(emb, opt, b1, b2, W1, W2, W3, y, out, out_size);
}

// round 9
// speedup vs baseline: 1.0918x; 1.0918x over previous
#include <cuda_runtime.h>
#include <math.h>

#define HID   1024
#define BSZ   16
#define NOPT  4
#define ROWS  (BSZ*NOPT)    // 64
#define TRUN  2
#define SEQ   1536
#define PLEN  512
#define QLEN  128

#define KSPLIT 32
#define KCHUNK (HID/KSPLIT)   // 32
#define NTILE  64

// Scratch (device globals — no allocation allowed)
__device__ float g_feats[ROWS*HID];
__device__ float g_h1[ROWS*HID];
__device__ float g_h2[ROWS*HID];
__device__ float g_loss_parts[BSZ];
__device__ unsigned g_cnt;     // 16-wide completion counter (reset in prep)

// ---------------------------------------------------------------------------
// f32x2 helpers (Blackwell packed fp32 pipe; PTX-only)
// ---------------------------------------------------------------------------
__device__ __forceinline__ unsigned long long bcast_f32x2(float v) {
    unsigned long long r;
    asm("mov.b64 %0, {%1, %1};" : "=l"(r) : "r"(__float_as_uint(v)));
    return r;
}
__device__ __forceinline__ void fma_f32x2(unsigned long long& acc,
                                          unsigned long long a,
                                          unsigned long long b) {
    asm("fma.rn.f32x2 %0, %1, %2, %0;" : "+l"(acc) : "l"(a), "l"(b));
}
__device__ __forceinline__ float lo_f(unsigned long long v) {
    return __uint_as_float((unsigned)(v & 0xFFFFFFFFull));
}
__device__ __forceinline__ float hi_f(unsigned long long v) {
    return __uint_as_float((unsigned)(v >> 32));
}

__device__ __forceinline__ long long opt_at(const void* p, bool is64, int i) {
    if (is64) return ((const long long*)p)[i];
    return (long long)((const int*)p)[i];
}

// ---------------------------------------------------------------------------
// 1) prep (R4 layout, 320 CTAs): blocks [0,256) bias-init h1/h2;
//    blocks [256,320) compute feats rows. Resets the gemv counter.
// ---------------------------------------------------------------------------
__global__ void __launch_bounds__(256)
prep_kernel(const float* __restrict__ emb, const void* __restrict__ opt_length,
            const float* __restrict__ b1, const float* __restrict__ b2) {
    if (blockIdx.x == 0 && threadIdx.x == 0) g_cnt = 0;

    if (blockIdx.x < 256) {
        int i = blockIdx.x * 256 + threadIdx.x;     // 0..65535
        int j = i & (HID - 1);
        g_h1[i] = b1[j];
        g_h2[i] = b2[j];
        return;
    }
    int row = blockIdx.x - 256;      // b*NOPT + o
    int b = row >> 2, o = row & 3;

    bool is64 = (((const int*)opt_length)[1] == 0);
    long long cs = 0;
    for (int i = 0; i <= o; i++) cs += opt_at(opt_length, is64, i);
    int ohead = PLEN + QLEN + (int)cs;
    int otail = ohead + (int)opt_at(opt_length, is64, o + 1) - 1;
    int pos[6] = {0, PLEN - 1, PLEN, PLEN + QLEN - 1, ohead, otail};

    int h4 = threadIdx.x * 4;
    float4 acc = make_float4(0.f, 0.f, 0.f, 0.f);
    #pragma unroll
    for (int t = 0; t < TRUN; t++) {
        const float* base = emb + (size_t)(t * BSZ + b) * SEQ * HID;
        #pragma unroll
        for (int p = 0; p < 6; p++) {
            float4 v = *(const float4*)(base + (size_t)pos[p] * HID + h4);
            acc.x += v.x; acc.y += v.y; acc.z += v.z; acc.w += v.w;
        }
    }
    const float s = 0.25f;
    *(float4*)(g_feats + (size_t)row * HID + h4) =
        make_float4(acc.x * s, acc.y * s, acc.z * s, acc.w * s);
}

// ---------------------------------------------------------------------------
// 2) Split-K GEMM (exact R4 version — measured good): out += A(64xK)@W(KxN),
//    64x64 tile, K-chunk 32, grid (16,32)=512 CTAs, 4x4 micro via FFMA2,
//    red.global.add.v4 epilogue onto bias-initialized out.
// ---------------------------------------------------------------------------
template <int LAYER>
__global__ void __launch_bounds__(256, 6)
gemm_kernel(const float* __restrict__ W) {
    __shared__ float As[KCHUNK][68];   // [k][row], pitch 68
    __shared__ float Ws[KCHUNK][64];   // [k][col]

    const float* A  = (LAYER == 0) ? g_feats : g_h1;
    float*      out = (LAYER == 0) ? g_h1    : g_h2;

    const int n0  = blockIdx.x * NTILE;
    const int k0  = blockIdx.y * KCHUNK;
    const int tid = threadIdx.x;

    {
        int kk4 = (tid & 7) * 4;
        int r   = tid >> 3;
        #pragma unroll
        for (int rr = 0; rr < 2; rr++) {
            int row = r + rr * 32;
            float4 v = *(const float4*)(A + (size_t)row * HID + k0 + kk4);
            if (LAYER == 1) {
                v.x = fmaxf(v.x, 0.f); v.y = fmaxf(v.y, 0.f);
                v.z = fmaxf(v.z, 0.f); v.w = fmaxf(v.w, 0.f);
            }
            As[kk4 + 0][row] = v.x;
            As[kk4 + 1][row] = v.y;
            As[kk4 + 2][row] = v.z;
            As[kk4 + 3][row] = v.w;
        }
    }
    {
        int c4 = (tid & 15) * 4;
        int kk = tid >> 4;
        #pragma unroll
        for (int i = 0; i < 2; i++) {
            int k = kk + i * 16;
            *(float4*)&Ws[k][c4] =
                *(const float4*)(W + (size_t)(k0 + k) * HID + n0 + c4);
        }
    }
    __syncthreads();

    const int c0 = (tid & 15) * 4;
    const int r0 = (tid >> 4) * 4;

    unsigned long long accP[4][2] = {};
    #pragma unroll
    for (int kk = 0; kk < KCHUNK; kk++) {
        ulonglong2 ap = *(const ulonglong2*)&As[kk][r0];
        float4 w = *(const float4*)&Ws[kk][c0];
        unsigned long long w0 = bcast_f32x2(w.x);
        unsigned long long w1 = bcast_f32x2(w.y);
        unsigned long long w2 = bcast_f32x2(w.z);
        unsigned long long w3 = bcast_f32x2(w.w);
        fma_f32x2(accP[0][0], ap.x, w0); fma_f32x2(accP[0][1], ap.y, w0);
        fma_f32x2(accP[1][0], ap.x, w1); fma_f32x2(accP[1][1], ap.y, w1);
        fma_f32x2(accP[2][0], ap.x, w2); fma_f32x2(accP[2][1], ap.y, w2);
        fma_f32x2(accP[3][0], ap.x, w3); fma_f32x2(accP[3][1], ap.y, w3);
    }

    #pragma unroll
    for (int i = 0; i < 4; i++) {
        int h = i >> 1;
        float v0 = (i & 1) ? hi_f(accP[0][h]) : lo_f(accP[0][h]);
        float v1 = (i & 1) ? hi_f(accP[1][h]) : lo_f(accP[1][h]);
        float v2 = (i & 1) ? hi_f(accP[2][h]) : lo_f(accP[2][h]);
        float v3 = (i & 1) ? hi_f(accP[3][h]) : lo_f(accP[3][h]);
        float* p = out + (size_t)(r0 + i) * HID + n0 + c0;
        asm volatile("red.global.add.v4.f32 [%0], {%1, %2, %3, %4};"
                     :: "l"(p), "f"(v0), "f"(v1), "f"(v2), "f"(v3) : "memory");
    }
}

// ---------------------------------------------------------------------------
// 3) gemv+loss, batch-per-CTA: 16 CTAs x 256 threads. CTA b computes its 4
//    logits (64 threads per row), the batch-LOCAL softmax loss term, and the
//    last finisher does the deterministic ordered mean over 16 parts.
// ---------------------------------------------------------------------------
__global__ void __launch_bounds__(256)
gemv_loss_kernel(const float* __restrict__ W3, const int* __restrict__ y,
                 float* __restrict__ out, int out_size) {
    __shared__ float red[8];     // one slot per warp; warp w covers row o=w>>1
    __shared__ float lsh[NOPT];

    const int b    = blockIdx.x;        // batch 0..15
    const int tid  = threadIdx.x;
    const int o    = tid >> 6;          // option 0..3
    const int lane = tid & 63;          // 0..63 within row group

    const float* h = g_h2 + (size_t)(b * NOPT + o) * HID;
    float s = 0.f;
    #pragma unroll
    for (int i = 0; i < 4; i++) {       // 64 lanes * 4 iters * float4 = 1024
        int k = (lane + i * 64) * 4;
        float4 hv = *(const float4*)(h + k);
        float4 wv = *(const float4*)(W3 + k);
        s += fmaxf(hv.x, 0.f) * wv.x + fmaxf(hv.y, 0.f) * wv.y
           + fmaxf(hv.z, 0.f) * wv.z + fmaxf(hv.w, 0.f) * wv.w;
    }
    #pragma unroll
    for (int off = 16; off; off >>= 1)
        s += __shfl_down_sync(0xFFFFFFFFu, s, off);
    if ((tid & 31) == 0) red[tid >> 5] = s;
    __syncthreads();

    if (tid < NOPT) lsh[tid] = red[2 * tid] + red[2 * tid + 1];
    __syncthreads();

    if (tid == 0) {
        float l0 = lsh[0], l1 = lsh[1], l2 = lsh[2], l3 = lsh[3];
        if (out_size >= ROWS) {
            out[b * NOPT + 0] = l0; out[b * NOPT + 1] = l1;
            out[b * NOPT + 2] = l2; out[b * NOPT + 3] = l3;
        }
        float m  = fmaxf(fmaxf(l0, l1), fmaxf(l2, l3));
        float se = expf(l0 - m) + expf(l1 - m) + expf(l2 - m) + expf(l3 - m);
        float lse = m + logf(se);
        int yy = y[b];
        float ly = (yy == 0) ? l0 : (yy == 1) ? l1 : (yy == 2) ? l2 : l3;
        g_loss_parts[b] = -(ly - lse);

        __threadfence();                        // release part
        unsigned t = atomicAdd(&g_cnt, 1u);
        if (t == BSZ - 1) {                     // last finisher: ordered mean
            __threadfence();                    // acquire all parts
            float loss = 0.f;
            #pragma unroll
            for (int i = 0; i < BSZ; i++) loss += __ldcg(&g_loss_parts[i]);
            loss /= (float)BSZ;
            if (out_size == 1)             out[0] = loss;
            else if (out_size >= ROWS + 1) out[ROWS] = loss;
        }
    }
}

// ---------------------------------------------------------------------------
// Launch — 4 kernels
// inputs: 0=embeddings 1=W1 2=b1 3=W2 4=b2 5=W3 6=y 7=opt_length
// ---------------------------------------------------------------------------
extern "C" void kernel_launch(void* const* d_in, const int* in_sizes, int n_in,
                              void* d_out, int out_size) {
    const float* emb = (const float*)d_in[0];
    const float* W1  = (const float*)d_in[1];
    const float* b1  = (const float*)d_in[2];
    const float* W2  = (const float*)d_in[3];
    const float* b2  = (const float*)d_in[4];
    const float* W3  = (const float*)d_in[5];
    const int*   y   = (const int*)d_in[6];
    const void*  opt = (const void*)d_in[7];
    float* out = (float*)d_out;

    prep_kernel<<<320, 256>>>(emb, opt, b1, b2);
    gemm_kernel<0><<<dim3(16, KSPLIT), 256>>>(W1);
    gemm_kernel<1><<<dim3(16, KSPLIT), 256>>>(W2);
    gemv_loss_kernel<<<BSZ, 256>>>(W3, y, out, out_size);
}